// round 12
// baseline (speedup 1.0000x reference)
#include <cuda_runtime.h>

#define WARPS 8
#define THREADS 256
#define NSTEP 10
#define XSTRIDE 48   // floats per padded row; 48 % 32 == 16 -> conflict-free LDS.64

__device__ __forceinline__ float setgt1(float a) {
    float r;
    asm("set.gt.f32.f32 %0, %1, %2;" : "=f"(r) : "f"(a), "f"(1.0f));
    return r;
}

// R11 structure (best: 268.6us, issue 86.7%) with the channel loop unrolled
// x4: cuts loop-control + address-IMAD slots and lets ptxas hoist the wv
// LDS.128s across iterations, interleaving one iteration's t-loop with the
// next one's loads. All arithmetic and summation order identical to R11
// (bit-exact), incl. the stride-33 smem transpose reduction.
__global__ void __launch_bounds__(THREADS, 4)
snn_kernel(const float* __restrict__ x, const float* __restrict__ convw,
           const float* __restrict__ convb, const float* __restrict__ fcw,
           const float* __restrict__ fcb, float* __restrict__ out, int nB)
{
    __shared__ __align__(16) float sx[WARPS][18 * XSTRIDE];
    __shared__ __align__(16) float sw01[4096];    // interleaved (w0_i, w1_i)
    __shared__ __align__(16) float scw4[8 * 12];  // per ch: w0..w8, bias, pad, pad

    const int tid  = threadIdx.x;
    const int warp = tid >> 5;
    const int lane = tid & 31;
    const long long b = (long long)blockIdx.x * WARPS + warp;

    for (int i = tid; i < 2048; i += THREADS) {
        sw01[2 * i]     = fcw[i];
        sw01[2 * i + 1] = fcw[2048 + i];
    }
    if (tid < 96) {
        int ch = tid / 12, k = tid % 12;
        float v = 0.0f;
        if (k < 9)       v = convw[ch * 9 + k];
        else if (k == 9) v = convb[ch];
        scw4[tid] = v;
    }

    float* sxw = sx[warp];
    #pragma unroll
    for (int i = lane; i < 18 * XSTRIDE; i += 32) sxw[i] = 0.0f;
    __syncwarp();

    if (b < nB) {
        const float4* xb = (const float4*)(x + b * 256);
        #pragma unroll
        for (int i = lane; i < 64; i += 32) {
            float4 v = xb[i];
            int p = i * 4;
            int y = p >> 4, xx = p & 15;
            float* d = &sxw[(y + 1) * XSTRIDE + xx + 1];
            d[0] = v.x; d[1] = v.y; d[2] = v.z; d[3] = v.w;
        }
    }
    __syncthreads();

    if (b < nB) {
        // 10 time steps x 2 output channels, scalar accumulators
        float o0[NSTEP], o1[NSTEP];
        #pragma unroll
        for (int t = 0; t < NSTEP; t++) { o0[t] = 0.0f; o1[t] = 0.0f; }

        #pragma unroll 1
        for (int rr = 0; rr < 4; rr++) {
            const int q  = lane + 32 * rr;   // pair index in channel
            const int y  = q >> 3;
            const int x0 = (q & 7) * 2;
            const float* rp = sxw + y * XSTRIDE + x0;
            // taps register-resident across the whole channel loop
            const float2 t00 = *(const float2*)(rp);
            const float2 t01 = *(const float2*)(rp + 2);
            const float2 t10 = *(const float2*)(rp + XSTRIDE);
            const float2 t11 = *(const float2*)(rp + XSTRIDE + 2);
            const float2 t20 = *(const float2*)(rp + 2 * XSTRIDE);
            const float2 t21 = *(const float2*)(rp + 2 * XSTRIDE + 2);

            const int qb = q * 2;            // flat even element within channel

            #pragma unroll 4
            for (int ch = 0; ch < 8; ch++) {
                // ---- all loads first: latency hides under the conv block ----
                const float4* cw4 = (const float4*)&scw4[ch * 12];
                const float4 wA = cw4[0];   // w0 w1 w2 w3
                const float4 wB = cw4[1];   // w4 w5 w6 w7
                const float4 wC = cw4[2];   // w8 bias - -
                const int ib = ch * 256 + qb;
                // wv = (w0_even, w1_even, w0_odd, w1_odd), one LDS.128
                const float4 wv = *(const float4*)&sw01[2 * ib];

                // scalar conv, op order identical to R1/R4/R5/R7/R10/R11
                float ca = wC.y, cb = wC.y;
                ca = fmaf(wA.x, t00.x, ca);  cb = fmaf(wA.x, t00.y, cb);
                ca = fmaf(wA.y, t00.y, ca);  cb = fmaf(wA.y, t01.x, cb);
                ca = fmaf(wA.z, t01.x, ca);  cb = fmaf(wA.z, t01.y, cb);
                ca = fmaf(wA.w, t10.x, ca);  cb = fmaf(wA.w, t10.y, cb);
                ca = fmaf(wB.x, t10.y, ca);  cb = fmaf(wB.x, t11.x, cb);
                ca = fmaf(wB.y, t11.x, ca);  cb = fmaf(wB.y, t11.y, cb);
                ca = fmaf(wB.z, t20.x, ca);  cb = fmaf(wB.z, t20.y, cb);
                ca = fmaf(wB.w, t20.y, ca);  cb = fmaf(wB.w, t21.x, cb);
                ca = fmaf(wC.x, t21.x, ca);  cb = fmaf(wC.x, t21.y, cb);

                // t = 0 peeled: m = 0.9*0 + c - 0 = c exactly
                float ma = ca, mb = cb;
                float sa = setgt1(ma);
                float sb = setgt1(mb);
                o0[0] = fmaf(sa, wv.x, o0[0]);
                o0[0] = fmaf(sb, wv.z, o0[0]);
                o1[0] = fmaf(sa, wv.y, o1[0]);
                o1[0] = fmaf(sb, wv.w, o1[0]);

                #pragma unroll
                for (int t = 1; t < NSTEP; t++) {
                    ma = fmaf(0.9f, ma, ca);   // beta*m + c   (FFMA-imm)
                    mb = fmaf(0.9f, mb, cb);
                    ma = ma - sa;              // - reset      (FADD)
                    mb = mb - sb;
                    sa = setgt1(ma);           // spk = m > 1  (FSET, alu)
                    sb = setgt1(mb);
                    // acc order: even half then odd half, per accumulator
                    o0[t] = fmaf(sa, wv.x, o0[t]);
                    o0[t] = fmaf(sb, wv.z, o0[t]);
                    o1[t] = fmaf(sa, wv.y, o1[t]);
                    o1[t] = fmaf(sb, wv.w, o1[t]);
                }
            }
        }

        // ---- smem-transpose warp reduction (input tile sxw is dead now) ----
        // stride 33: slot r, lane l -> banks (r + l) % 32: conflict-free both ways.
        __syncwarp();
        #pragma unroll
        for (int t = 0; t < NSTEP; t++) {
            sxw[t * 33 + lane]            = o0[t];
            sxw[(NSTEP + t) * 33 + lane]  = o1[t];
        }
        __syncwarp();
        if (lane < 2 * NSTEP) {
            const float* p = &sxw[lane * 33];
            float tot = 0.0f;
            #pragma unroll
            for (int j = 0; j < 32; j++) tot += p[j];
            sxw[20 * 33 + lane] = tot;
        }
        __syncwarp();

        if (lane == 0) {
            const float fb0 = fcb[0], fb1 = fcb[1];
            float m20 = 0.f, m21 = 0.f, s20 = 0.f, s21 = 0.f, a0 = 0.f, a1 = 0.f;
            #pragma unroll
            for (int t = 0; t < NSTEP; t++) {
                float c0 = sxw[20 * 33 + t]         + fb0;
                float c1 = sxw[20 * 33 + NSTEP + t] + fb1;
                m20 = fmaf(0.9f, m20, c0) - s20;
                m21 = fmaf(0.9f, m21, c1) - s21;
                s20 = (m20 > 1.0f) ? 1.0f : 0.0f;
                s21 = (m21 > 1.0f) ? 1.0f : 0.0f;
                a0 += s20;
                a1 += s21;
            }
            out[b * 2 + 0] = a0;
            out[b * 2 + 1] = a1;
        }
    }
}

extern "C" void kernel_launch(void* const* d_in, const int* in_sizes, int n_in,
                              void* d_out, int out_size) {
    const float* x  = (const float*)d_in[0];
    const float* cw = (const float*)d_in[1];
    const float* cb = (const float*)d_in[2];
    const float* fw = (const float*)d_in[3];
    const float* fb = (const float*)d_in[4];
    float* out = (float*)d_out;

    const int nB = in_sizes[0] / 256;
    const int blocks = (nB + WARPS - 1) / WARPS;
    snn_kernel<<<blocks, THREADS>>>(x, cw, cb, fw, fb, out, nB);
}

// round 14
// speedup vs baseline: 1.0162x; 1.0162x over previous
#include <cuda_runtime.h>

#define WARPS 8
#define THREADS 256
#define NSTEP 10
#define XSTRIDE 48   // floats per padded row; 48 % 32 == 16 -> conflict-free LDS.64
#define RSTRIDE 36   // epilogue transpose stride: mult of 4 -> 16B-aligned rows

__device__ __forceinline__ float setgt1(float a) {
    float r;
    asm("set.gt.f32.f32 %0, %1, %2;" : "=f"(r) : "f"(a), "f"(1.0f));
    return r;
}

// R11 main loop (best: 268.6us) byte-identical; epilogue transpose reduction
// with ROW STRIDE 36 (multiple of 4 floats -> every row base is 16B-aligned,
// fixing R13's misaligned LDS.128). Stores hit banks (4t+lane)%32 (all
// distinct); LDS.128 phases of 8 lanes start at disjoint 4-bank groups.
// Row sums use 4 independent float4 accumulator chains.
__global__ void __launch_bounds__(THREADS, 4)
snn_kernel(const float* __restrict__ x, const float* __restrict__ convw,
           const float* __restrict__ convb, const float* __restrict__ fcw,
           const float* __restrict__ fcb, float* __restrict__ out, int nB)
{
    __shared__ __align__(16) float sx[WARPS][18 * XSTRIDE];
    __shared__ __align__(16) float sw01[4096];    // interleaved (w0_i, w1_i)
    __shared__ __align__(16) float scw4[8 * 12];  // per ch: w0..w8, bias, pad, pad

    const int tid  = threadIdx.x;
    const int warp = tid >> 5;
    const int lane = tid & 31;
    const long long b = (long long)blockIdx.x * WARPS + warp;

    for (int i = tid; i < 2048; i += THREADS) {
        sw01[2 * i]     = fcw[i];
        sw01[2 * i + 1] = fcw[2048 + i];
    }
    if (tid < 96) {
        int ch = tid / 12, k = tid % 12;
        float v = 0.0f;
        if (k < 9)       v = convw[ch * 9 + k];
        else if (k == 9) v = convb[ch];
        scw4[tid] = v;
    }

    float* sxw = sx[warp];
    #pragma unroll
    for (int i = lane; i < 18 * XSTRIDE; i += 32) sxw[i] = 0.0f;
    __syncwarp();

    if (b < nB) {
        const float4* xb = (const float4*)(x + b * 256);
        #pragma unroll
        for (int i = lane; i < 64; i += 32) {
            float4 v = xb[i];
            int p = i * 4;
            int y = p >> 4, xx = p & 15;
            float* d = &sxw[(y + 1) * XSTRIDE + xx + 1];
            d[0] = v.x; d[1] = v.y; d[2] = v.z; d[3] = v.w;
        }
    }
    __syncthreads();

    if (b < nB) {
        // 10 time steps x 2 output channels, scalar accumulators
        float o0[NSTEP], o1[NSTEP];
        #pragma unroll
        for (int t = 0; t < NSTEP; t++) { o0[t] = 0.0f; o1[t] = 0.0f; }

        #pragma unroll 1
        for (int rr = 0; rr < 4; rr++) {
            const int q  = lane + 32 * rr;   // pair index in channel
            const int y  = q >> 3;
            const int x0 = (q & 7) * 2;
            const float* rp = sxw + y * XSTRIDE + x0;
            // taps register-resident across the whole channel loop
            const float2 t00 = *(const float2*)(rp);
            const float2 t01 = *(const float2*)(rp + 2);
            const float2 t10 = *(const float2*)(rp + XSTRIDE);
            const float2 t11 = *(const float2*)(rp + XSTRIDE + 2);
            const float2 t20 = *(const float2*)(rp + 2 * XSTRIDE);
            const float2 t21 = *(const float2*)(rp + 2 * XSTRIDE + 2);

            const int qb = q * 2;            // flat even element within channel

            #pragma unroll 2
            for (int ch = 0; ch < 8; ch++) {
                // ---- all loads first: latency hides under the conv block ----
                const float4* cw4 = (const float4*)&scw4[ch * 12];
                const float4 wA = cw4[0];   // w0 w1 w2 w3
                const float4 wB = cw4[1];   // w4 w5 w6 w7
                const float4 wC = cw4[2];   // w8 bias - -
                const int ib = ch * 256 + qb;
                // wv = (w0_even, w1_even, w0_odd, w1_odd), one LDS.128
                const float4 wv = *(const float4*)&sw01[2 * ib];

                // scalar conv, op order identical to R1/R4/R5/R7/R10/R11
                float ca = wC.y, cb = wC.y;
                ca = fmaf(wA.x, t00.x, ca);  cb = fmaf(wA.x, t00.y, cb);
                ca = fmaf(wA.y, t00.y, ca);  cb = fmaf(wA.y, t01.x, cb);
                ca = fmaf(wA.z, t01.x, ca);  cb = fmaf(wA.z, t01.y, cb);
                ca = fmaf(wA.w, t10.x, ca);  cb = fmaf(wA.w, t10.y, cb);
                ca = fmaf(wB.x, t10.y, ca);  cb = fmaf(wB.x, t11.x, cb);
                ca = fmaf(wB.y, t11.x, ca);  cb = fmaf(wB.y, t11.y, cb);
                ca = fmaf(wB.z, t20.x, ca);  cb = fmaf(wB.z, t20.y, cb);
                ca = fmaf(wB.w, t20.y, ca);  cb = fmaf(wB.w, t21.x, cb);
                ca = fmaf(wC.x, t21.x, ca);  cb = fmaf(wC.x, t21.y, cb);

                // t = 0 peeled: m = 0.9*0 + c - 0 = c exactly
                float ma = ca, mb = cb;
                float sa = setgt1(ma);
                float sb = setgt1(mb);
                o0[0] = fmaf(sa, wv.x, o0[0]);
                o0[0] = fmaf(sb, wv.z, o0[0]);
                o1[0] = fmaf(sa, wv.y, o1[0]);
                o1[0] = fmaf(sb, wv.w, o1[0]);

                #pragma unroll
                for (int t = 1; t < NSTEP; t++) {
                    ma = fmaf(0.9f, ma, ca);   // beta*m + c   (FFMA-imm)
                    mb = fmaf(0.9f, mb, cb);
                    ma = ma - sa;              // - reset      (FADD)
                    mb = mb - sb;
                    sa = setgt1(ma);           // spk = m > 1  (FSET, alu)
                    sb = setgt1(mb);
                    // acc order: even half then odd half, per accumulator
                    o0[t] = fmaf(sa, wv.x, o0[t]);
                    o0[t] = fmaf(sb, wv.z, o0[t]);
                    o1[t] = fmaf(sa, wv.y, o1[t]);
                    o1[t] = fmaf(sb, wv.w, o1[t]);
                }
            }
        }

        // ---- smem-transpose warp reduction (input tile sxw is dead now) ----
        __syncwarp();
        #pragma unroll
        for (int t = 0; t < NSTEP; t++) {
            sxw[t * RSTRIDE + lane]            = o0[t];
            sxw[(NSTEP + t) * RSTRIDE + lane]  = o1[t];
        }
        __syncwarp();
        if (lane < 2 * NSTEP) {
            // row r = lane: 32 contiguous floats at sxw[r*36]; base 16B-aligned.
            const float4* p = (const float4*)&sxw[lane * RSTRIDE];
            float4 s0 = p[0], s1 = p[1], s2 = p[2], s3 = p[3];
            const float4 q4 = p[4], q5 = p[5], q6 = p[6], q7 = p[7];
            s0.x += q4.x; s0.y += q4.y; s0.z += q4.z; s0.w += q4.w;
            s1.x += q5.x; s1.y += q5.y; s1.z += q5.z; s1.w += q5.w;
            s2.x += q6.x; s2.y += q6.y; s2.z += q6.z; s2.w += q6.w;
            s3.x += q7.x; s3.y += q7.y; s3.z += q7.z; s3.w += q7.w;
            s0.x += s1.x; s0.y += s1.y; s0.z += s1.z; s0.w += s1.w;
            s2.x += s3.x; s2.y += s3.y; s2.z += s3.z; s2.w += s3.w;
            s0.x += s2.x; s0.y += s2.y; s0.z += s2.z; s0.w += s2.w;
            float tot = (s0.x + s0.y) + (s0.z + s0.w);
            sxw[21 * RSTRIDE + lane] = tot;
        }
        __syncwarp();

        if (lane == 0) {
            const float fb0 = fcb[0], fb1 = fcb[1];
            float m20 = 0.f, m21 = 0.f, s20 = 0.f, s21 = 0.f, a0 = 0.f, a1 = 0.f;
            #pragma unroll
            for (int t = 0; t < NSTEP; t++) {
                float c0 = sxw[21 * RSTRIDE + t]         + fb0;
                float c1 = sxw[21 * RSTRIDE + NSTEP + t] + fb1;
                m20 = fmaf(0.9f, m20, c0) - s20;
                m21 = fmaf(0.9f, m21, c1) - s21;
                s20 = (m20 > 1.0f) ? 1.0f : 0.0f;
                s21 = (m21 > 1.0f) ? 1.0f : 0.0f;
                a0 += s20;
                a1 += s21;
            }
            out[b * 2 + 0] = a0;
            out[b * 2 + 1] = a1;
        }
    }
}

extern "C" void kernel_launch(void* const* d_in, const int* in_sizes, int n_in,
                              void* d_out, int out_size) {
    const float* x  = (const float*)d_in[0];
    const float* cw = (const float*)d_in[1];
    const float* cb = (const float*)d_in[2];
    const float* fw = (const float*)d_in[3];
    const float* fb = (const float*)d_in[4];
    float* out = (float*)d_out;

    const int nB = in_sizes[0] / 256;
    const int blocks = (nB + WARPS - 1) / WARPS;
    snn_kernel<<<blocks, THREADS>>>(x, cw, cb, fw, fb, out, nB);
}